// round 10
// baseline (speedup 1.0000x reference)
#include <cuda_runtime.h>
#include <cuda_fp16.h>
#include <cstdint>

// ---------------- problem constants ----------------
#define BATCH   8
#define DMODEL  256
#define NH      8
#define NLVL    4
#define NPT     4
#define DH      32
#define NLAYERS 6
#define DFF     1024
#define LQ      5440            // 4096 + 1024 + 256 + 64
#define MROWS   (BATCH * LQ)    // 43520

typedef __half f16;

// ---------------- scratch (device globals; no allocation allowed) ----------------
__device__ __align__(16) float g_x   [MROWS * DMODEL];
__device__ __align__(16) float g_pos [MROWS * DMODEL];
__device__ __align__(16) float g_off [MROWS * 384];     // offsets(256)+logits(128)
__device__ __align__(16) float g_tmp [MROWS * DMODEL];

__device__ __align__(16) f16 g_valh[MROWS * DMODEL];    // fp16 value (sampler input)
__device__ __align__(16) f16 g_xh [MROWS * DMODEL];
__device__ __align__(16) f16 g_qh [MROWS * DMODEL];
__device__ __align__(16) f16 g_ach[MROWS * DMODEL];
__device__ __align__(16) f16 g_hh [MROWS * DFF];

// fp16 weights, transposed to [N, K] K-major
__device__ __align__(16) f16 g_wv_h [NLAYERS * 256 * 256];
__device__ __align__(16) f16 g_woa_h[NLAYERS * 384 * 256];   // Wo rows 0-255, Wa rows 256-383
__device__ __align__(16) f16 g_wu_h [NLAYERS * 256 * 256];
__device__ __align__(16) f16 g_w1_h [NLAYERS * 1024 * 256];
__device__ __align__(16) f16 g_w2_h [NLAYERS * 256 * 1024];
__device__ __align__(16) float g_boa [NLAYERS * 384];

// ---------------- low-level helpers ----------------
__device__ __forceinline__ uint32_t smem_u32(const void* p) {
    uint32_t a;
    asm("{ .reg .u64 t; cvta.to.shared.u64 t, %1; cvt.u32.u64 %0, t; }"
        : "=r"(a) : "l"(p));
    return a;
}
__device__ __forceinline__ void ldm4(uint32_t* r, uint32_t addr) {
    asm volatile("ldmatrix.sync.aligned.m8n8.x4.shared.b16 {%0,%1,%2,%3}, [%4];"
                 : "=r"(r[0]), "=r"(r[1]), "=r"(r[2]), "=r"(r[3]) : "r"(addr));
}
__device__ __forceinline__ void mma16816(float* c, const uint32_t* a,
                                         const uint32_t* b) {
    asm volatile(
        "mma.sync.aligned.m16n8k16.row.col.f32.f16.f16.f32 "
        "{%0,%1,%2,%3}, {%4,%5,%6,%7}, {%8,%9}, {%0,%1,%2,%3};"
        : "+f"(c[0]), "+f"(c[1]), "+f"(c[2]), "+f"(c[3])
        : "r"(a[0]), "r"(a[1]), "r"(a[2]), "r"(a[3]), "r"(b[0]), "r"(b[1]));
}
__device__ __forceinline__ uint32_t h2u(__half2 v) {
    return *reinterpret_cast<uint32_t*>(&v);
}
#define CP_ASYNC16(d, s) \
    asm volatile("cp.async.cg.shared.global [%0], [%1], 16;" :: "r"(d), "l"(s))
#define CP_COMMIT() asm volatile("cp.async.commit_group;" ::: "memory")
#define CP_WAIT(n)  asm volatile("cp.async.wait_group %0;" :: "n"(n) : "memory")

// ---------------- merged weight prep ----------------
__global__ void prep_kernel(
    const float* __restrict__ Wv, const float* __restrict__ Wo,
    const float* __restrict__ Wa, const float* __restrict__ Wout,
    const float* __restrict__ W1, const float* __restrict__ W2,
    f16* __restrict__ wvh, f16* __restrict__ woah, f16* __restrict__ wuh,
    f16* __restrict__ w1h, f16* __restrict__ w2h)
{
    __shared__ float t[32][33];
    int bid = blockIdx.x;
    const float* W; f16* hi;
    int K, N, Ntot, rowoff, tpl;
    if (bid < 384)       { W = Wv;   hi = wvh;  K = 256;  N = 256;  Ntot = 256;  rowoff = 0;   tpl = 64;  }
    else if (bid < 768)  { bid -= 384;  W = Wo;   hi = woah; K = 256;  N = 256;  Ntot = 384;  rowoff = 0;   tpl = 64;  }
    else if (bid < 960)  { bid -= 768;  W = Wa;   hi = woah; K = 256;  N = 128;  Ntot = 384;  rowoff = 256; tpl = 32;  }
    else if (bid < 1344) { bid -= 960;  W = Wout; hi = wuh;  K = 256;  N = 256;  Ntot = 256;  rowoff = 0;   tpl = 64;  }
    else if (bid < 2880) { bid -= 1344; W = W1;   hi = w1h;  K = 256;  N = 1024; Ntot = 1024; rowoff = 0;   tpl = 256; }
    else                 { bid -= 2880; W = W2;   hi = w2h;  K = 1024; N = 256;  Ntot = 256;  rowoff = 0;   tpl = 256; }
    const int l = bid / tpl, tt = bid % tpl;
    const int nt = N / 32;
    const int n0 = (tt % nt) * 32, k0 = (tt / nt) * 32;

    const float* Wl = W + (size_t)l * K * N;
    t[threadIdx.y][threadIdx.x] = Wl[(size_t)(k0 + threadIdx.y) * N + n0 + threadIdx.x];
    __syncthreads();
    const size_t o = ((size_t)l * Ntot + rowoff + n0 + threadIdx.y) * K + k0 + threadIdx.x;
    hi[o] = __float2half_rn(t[threadIdx.x][threadIdx.y]);
}

__global__ void bpack_kernel(const float* __restrict__ bo, const float* __restrict__ ba,
                             float* __restrict__ boa)
{
    const int l = blockIdx.x, t = threadIdx.x;   // 384 threads
    boa[l * 384 + t] = (t < 256) ? bo[l * 256 + t] : ba[l * 128 + (t - 256)];
}

// ---------------- pipelined fp16 mma.sync GEMM core (single pass) ----------------
// C = A[M,K] @ B[N,K]^T + bias. CTA 128x128, 8 warps 2x4, warp tile 64x32,
// BK=32, cp.async 4-stage pipeline.
// mode 0: fp32 out.  mode 1: relu + fp16 out.  mode 2: fp16 out (no relu).
#define GPITCH 80
#define TILESZ 10240
#define STGSZ  20480   // A + B
#define NSTG   4

__device__ __forceinline__ void gemm_core(
    const f16* __restrict__ A, const f16* __restrict__ B,
    const float* __restrict__ bias, float* __restrict__ Cf,
    f16* __restrict__ Ch,
    int K, int N, int mode, int m0, int n0, uint8_t* sm)
{
    const uint32_t sb = smem_u32(sm);
    const int tid = threadIdx.x;
    const int wid = tid >> 5, lane = tid & 31;
    const int wm = wid >> 2, wn = wid & 3;
    const int m0w = wm * 64, n0w = wn * 32;
    const int tlq = lane >> 3, rlq = lane & 7;

    const f16* gA = A + (size_t)m0 * K;
    const f16* gB = B + (size_t)n0 * K;

    float acc[4][4][4];
#pragma unroll
    for (int i = 0; i < 4; i++)
#pragma unroll
        for (int j = 0; j < 4; j++)
#pragma unroll
            for (int c = 0; c < 4; c++) acc[i][j][c] = 0.f;

    const int nchunk = K >> 5;

    auto docopy = [&](int ch) {
        const int k0 = ch << 5;
        const uint32_t sbase = sb + (uint32_t)(ch % NSTG) * STGSZ;
#pragma unroll
        for (int j = 0; j < 4; j++) {
            const int buf = j >> 1;                  // 0=A, 1=B
            const int s = tid + ((j & 1) << 8);
            const int row = s >> 2, seg = s & 3;
            const f16* g = (buf ? gB : gA) + (size_t)row * K + k0 + seg * 8;
            const uint32_t d = sbase + buf * TILESZ + row * GPITCH + seg * 16;
            CP_ASYNC16(d, g);
        }
        CP_COMMIT();
    };

    for (int p = 0; p < NSTG - 1 && p < nchunk; p++) docopy(p);
    for (int ch = 0; ch < nchunk; ch++) {
        if (ch + NSTG - 1 < nchunk) { docopy(ch + NSTG - 1); CP_WAIT(NSTG - 1); }
        else if (ch + 1 < nchunk)   { CP_WAIT(1); }
        else                        { CP_WAIT(0); }
        __syncthreads();

        const uint32_t soff = sb + (uint32_t)(ch % NSTG) * STGSZ;
#pragma unroll
        for (int ks = 0; ks < 2; ks++) {
            const int kk = ks * 16;
            uint32_t af[16], bfr[8];

#pragma unroll
            for (int mi = 0; mi < 4; mi++) {
                const int r = m0w + mi * 16 + rlq + ((tlq & 1) << 3);
                const int kc = kk + ((tlq >> 1) << 3);
                ldm4(af + mi * 4, soff + r * GPITCH + kc * 2);
            }
#pragma unroll
            for (int nj = 0; nj < 2; nj++) {
                const int r = n0w + nj * 16 + rlq + ((tlq >> 1) << 3);
                const int kc = kk + ((tlq & 1) << 3);
                ldm4(bfr + nj * 4, soff + TILESZ + r * GPITCH + kc * 2);
            }
#pragma unroll
            for (int mi = 0; mi < 4; mi++)
#pragma unroll
                for (int ni = 0; ni < 4; ni++) {
                    uint32_t b2r[2] = {bfr[(ni >> 1) * 4 + (ni & 1) * 2],
                                       bfr[(ni >> 1) * 4 + (ni & 1) * 2 + 1]};
                    mma16816(acc[mi][ni], af + mi * 4, b2r);
                }
        }
        __syncthreads();
    }

    const int g = lane >> 2, tg = lane & 3;
#pragma unroll
    for (int mi = 0; mi < 4; mi++) {
        const int r0 = m0 + m0w + mi * 16 + g;
#pragma unroll
        for (int ni = 0; ni < 4; ni++) {
            const int col = n0 + n0w + ni * 8 + tg * 2;
            const float b0 = bias[col], b1 = bias[col + 1];
            float v00 = acc[mi][ni][0] + b0, v01 = acc[mi][ni][1] + b1;
            float v10 = acc[mi][ni][2] + b0, v11 = acc[mi][ni][3] + b1;
            if (mode == 0) {
                *(float2*)(Cf + (size_t)r0 * N + col)       = make_float2(v00, v01);
                *(float2*)(Cf + (size_t)(r0 + 8) * N + col) = make_float2(v10, v11);
            } else {
                if (mode == 1) {
                    v00 = fmaxf(v00, 0.f); v01 = fmaxf(v01, 0.f);
                    v10 = fmaxf(v10, 0.f); v11 = fmaxf(v11, 0.f);
                }
                *(uint32_t*)(Ch + (size_t)r0 * N + col) =
                    h2u(__halves2half2(__float2half_rn(v00), __float2half_rn(v01)));
                *(uint32_t*)(Ch + (size_t)(r0 + 8) * N + col) =
                    h2u(__halves2half2(__float2half_rn(v10), __float2half_rn(v11)));
            }
        }
    }
}

__global__ void __launch_bounds__(256, 2) mma_gemm(
    const f16* __restrict__ A, const f16* __restrict__ B,
    const float* __restrict__ bias, float* __restrict__ Cf,
    f16* __restrict__ Ch, int K, int N, int mode)
{
    extern __shared__ __align__(16) uint8_t sm[];
    gemm_core(A, B, bias, Cf, Ch, K, N, mode,
              blockIdx.y * 128, blockIdx.x * 128, sm);
}

// fused value + offsets/logits projections (independent, share a launch)
// grid.x: 0-1 = value tiles (N=256, fp16 out), 2-4 = proj tiles (N=384, fp32 out)
__global__ void __launch_bounds__(256, 2) proj_gemm(
    const f16* __restrict__ xh, const f16* __restrict__ wvh,
    const float* __restrict__ bv, f16* __restrict__ vbh,
    const f16* __restrict__ qh, const f16* __restrict__ woah,
    const float* __restrict__ boa, float* __restrict__ ob)
{
    extern __shared__ __align__(16) uint8_t sm[];
    const int m0 = blockIdx.y * 128;
    if (blockIdx.x < 2) {
        gemm_core(xh, wvh, bv, nullptr, vbh, 256, 256, 2, m0, blockIdx.x * 128, sm);
    } else {
        gemm_core(qh, woah, boa, ob, nullptr, 256, 384, 0, m0,
                  (blockIdx.x - 2) * 128, sm);
    }
}

// ---------------- non-GEMM kernels ----------------
__device__ __forceinline__ float warp_sum(float v) {
#pragma unroll
    for (int o = 16; o > 0; o >>= 1) v += __shfl_xor_sync(0xffffffffu, v, o);
    return v;
}
__device__ __forceinline__ float half_sum16(float v) {
#pragma unroll
    for (int o = 8; o > 0; o >>= 1) v += __shfl_xor_sync(0xffffffffu, v, o);
    return v;
}
__device__ __forceinline__ float half_max16(float v) {
#pragma unroll
    for (int o = 8; o > 0; o >>= 1) v = fmaxf(v, __shfl_xor_sync(0xffffffffu, v, o));
    return v;
}

// flatten: (B,D,H,W) -> x fp32, pos fp32, x fp16, q=x+pos fp16
__global__ void flatten_kernel(const float* __restrict__ s0, const float* __restrict__ s1,
                               const float* __restrict__ s2, const float* __restrict__ s3,
                               const float* __restrict__ p0, const float* __restrict__ p1,
                               const float* __restrict__ p2, const float* __restrict__ p3,
                               const float* __restrict__ lenc,
                               float* __restrict__ x, float* __restrict__ pos,
                               f16* __restrict__ xh, f16* __restrict__ qh)
{
    __shared__ float ts[32][33];
    __shared__ float tp[32][33];
    const int b  = blockIdx.z;
    const int q0 = blockIdx.x * 32;
    const int d0 = blockIdx.y * 32;

    int l, start, HW;
    const float *src, *pp;
    if (q0 < 4096)      { l = 0; start = 0;    HW = 4096; src = s0; pp = p0; }
    else if (q0 < 5120) { l = 1; start = 4096; HW = 1024; src = s1; pp = p1; }
    else if (q0 < 5376) { l = 2; start = 5120; HW = 256;  src = s2; pp = p2; }
    else                { l = 3; start = 5376; HW = 64;   src = s3; pp = p3; }

    const int pix0 = q0 - start;
    const int tx = threadIdx.x, ty = threadIdx.y;

    long sidx = ((long)b * DMODEL + (d0 + ty)) * HW + pix0 + tx;
    ts[ty][tx] = src[sidx];
    tp[ty][tx] = pp[sidx];
    __syncthreads();

    const int q  = q0 + ty;
    const int dd = d0 + tx;
    const size_t oidx = ((size_t)b * LQ + q) * DMODEL + dd;
    const float xv = ts[tx][ty];
    const float pv = tp[tx][ty] + lenc[l * DMODEL + dd];
    x[oidx]   = xv;
    pos[oidx] = pv;
    xh[oidx] = __float2half_rn(xv);
    qh[oidx] = __float2half_rn(xv + pv);
}

// deformable sampling + fused softmax; one warp per (b,q,h)
// tap-parallel: 4 tap-groups x 8 lanes, each lane holds 4 channels (fp16 value)
__global__ void __launch_bounds__(256) sample_kernel(
    const f16* __restrict__ val, const float* __restrict__ proj,
    f16* __restrict__ acch)
{
    const int gwid = (blockIdx.x * blockDim.x + threadIdx.x) >> 5;
    const int lane = threadIdx.x & 31;
    const int h = gwid % NH;
    const int q = (gwid / NH) % LQ;
    const int b = gwid / (NH * LQ);

    const size_t rowq = (size_t)b * LQ + q;
    const float* pr = proj + rowq * 384;

    float lv = pr[256 + h * 16 + (lane & 15)];
    float mx = half_max16(lv);
    float e  = __expf(lv - mx);
    float s  = half_sum16(e);
    const float wgt = e / s;

    int W0, start0;
    if (q < 4096)      { W0 = 64; start0 = 0;    }
    else if (q < 5120) { W0 = 32; start0 = 4096; }
    else if (q < 5376) { W0 = 16; start0 = 5120; }
    else               { W0 = 8;  start0 = 5376; }
    const int pix = q - start0;
    const float refx = ((pix % W0) + 0.5f) / (float)W0;
    const float refy = ((pix / W0) + 0.5f) / (float)W0;

    const float* ob = pr + h * 32;
    const int tap = lane >> 3;
    const int tdx = tap & 1, tdy = tap >> 1;
    const int ch4 = (lane & 7) * 4;

    const int Ls[4] = {64, 32, 16, 8};
    const int Ss[4] = {0, 4096, 5120, 5376};
    float4 a4 = make_float4(0.f, 0.f, 0.f, 0.f);

#pragma unroll
    for (int l = 0; l < NLVL; l++) {
        const int   HH = Ls[l];
        const float fH = (float)HH;
        const f16* vb = val + ((size_t)b * LQ + Ss[l]) * (NH * DH) + h * DH + ch4;
#pragma unroll
        for (int p = 0; p < NPT; p++) {
            const int si = l * NPT + p;
            const float ox = ob[si * 2];
            const float oy = ob[si * 2 + 1];
            const float aw = __shfl_sync(0xffffffffu, wgt, si);
            const float xx = refx * fH + ox - 0.5f;
            const float yy = refy * fH + oy - 0.5f;
            const float xf = floorf(xx), yf = floorf(yy);
            const float dx = xx - xf, dy = yy - yf;
            const int xi = (int)xf + tdx;
            const int yi = (int)yf + tdy;
            const float wt = (tdx ? dx : 1.f - dx) * (tdy ? dy : 1.f - dy) * aw;
            if (xi >= 0 && xi < HH && yi >= 0 && yi < HH) {
                const uint2 raw = *(const uint2*)(vb + (size_t)(yi * HH + xi) * (NH * DH));
                const __half2 p01 = *reinterpret_cast<const __half2*>(&raw.x);
                const __half2 p23 = *reinterpret_cast<const __half2*>(&raw.y);
                const float2 f01 = __half22float2(p01);
                const float2 f23 = __half22float2(p23);
                a4.x += wt * f01.x; a4.y += wt * f01.y;
                a4.z += wt * f23.x; a4.w += wt * f23.y;
            }
        }
    }
#pragma unroll
    for (int o = 8; o <= 16; o <<= 1) {
        a4.x += __shfl_xor_sync(0xffffffffu, a4.x, o);
        a4.y += __shfl_xor_sync(0xffffffffu, a4.y, o);
        a4.z += __shfl_xor_sync(0xffffffffu, a4.z, o);
        a4.w += __shfl_xor_sync(0xffffffffu, a4.w, o);
    }
    if (tap == 0) {
        const size_t oi = (rowq * NH + h) * DH + ch4;
        *(uint2*)(acch + oi) = make_uint2(
            h2u(__halves2half2(__float2half_rn(a4.x), __float2half_rn(a4.y))),
            h2u(__halves2half2(__float2half_rn(a4.z), __float2half_rn(a4.w))));
    }
}

// fused residual-add + LayerNorm; optional fp16 out; optional q=out+pos fp16
__global__ void __launch_bounds__(256) add_ln_kernel(
    const float* __restrict__ x, const float* __restrict__ r,
    const float* __restrict__ g, const float* __restrict__ bta,
    float* __restrict__ out,
    f16* __restrict__ oh,
    const float* __restrict__ pos, f16* __restrict__ qh,
    int flags)
{
    const int row  = blockIdx.x * 8 + (threadIdx.x >> 5);
    const int lane = threadIdx.x & 31;
    const size_t base = (size_t)row * DMODEL;
    const float* xr = x + base;
    const float* rr = r + base;

    float v[8];
    float sum = 0.f;
#pragma unroll
    for (int k = 0; k < 8; k++) {
        v[k] = xr[lane + 32 * k] + rr[lane + 32 * k];
        sum += v[k];
    }
    sum = warp_sum(sum);
    const float mu = sum * (1.f / 256.f);
    float vs = 0.f;
#pragma unroll
    for (int k = 0; k < 8; k++) { float d = v[k] - mu; vs += d * d; }
    vs = warp_sum(vs) * (1.f / 256.f);
    const float inv = rsqrtf(vs + 1e-5f);
#pragma unroll
    for (int k = 0; k < 8; k++) {
        const int c = lane + 32 * k;
        const float o = (v[k] - mu) * inv * g[c] + bta[c];
        out[base + c] = o;
        if (flags & 1) oh[base + c] = __float2half_rn(o);
        if (flags & 2) qh[base + c] = __float2half_rn(o + pos[base + c]);
    }
}

// ---------------- host orchestration ----------------
#define SMEM_GEMM (NSTG * STGSZ)

static void tcgemm(const f16* A, const f16* B, const float* bias,
                   float* Cf, f16* Ch, int K, int N, int mode)
{
    dim3 grid(N / 128, MROWS / 128);
    mma_gemm<<<grid, 256, SMEM_GEMM>>>(A, B, bias, Cf, Ch, K, N, mode);
}

extern "C" void kernel_launch(void* const* d_in, const int* in_sizes, int n_in,
                              void* d_out, int out_size)
{
    cudaFuncSetAttribute(mma_gemm,  cudaFuncAttributeMaxDynamicSharedMemorySize, SMEM_GEMM);
    cudaFuncSetAttribute(proj_gemm, cudaFuncAttributeMaxDynamicSharedMemorySize, SMEM_GEMM);

    // inputs may arrive interleaved (src0,pos0,src1,pos1,...) per dict order
    const float* src[4];
    const float* pos[4];
    if (in_sizes[1] == in_sizes[0]) {
        for (int i = 0; i < 4; i++) {
            src[i] = (const float*)d_in[2 * i];
            pos[i] = (const float*)d_in[2 * i + 1];
        }
    } else {
        for (int i = 0; i < 4; i++) {
            src[i] = (const float*)d_in[i];
            pos[i] = (const float*)d_in[4 + i];
        }
    }
    const float* lenc  = (const float*)d_in[8];
    const float* Wv    = (const float*)d_in[9];
    const float* bv    = (const float*)d_in[10];
    const float* Wo    = (const float*)d_in[11];
    const float* bo    = (const float*)d_in[12];
    const float* Wa    = (const float*)d_in[13];
    const float* ba    = (const float*)d_in[14];
    const float* Wout  = (const float*)d_in[15];
    const float* bout  = (const float*)d_in[16];
    const float* ln1g  = (const float*)d_in[17];
    const float* ln1b  = (const float*)d_in[18];
    const float* W1    = (const float*)d_in[19];
    const float* b1    = (const float*)d_in[20];
    const float* W2    = (const float*)d_in[21];
    const float* b2    = (const float*)d_in[22];
    const float* ln2g  = (const float*)d_in[23];
    const float* ln2b  = (const float*)d_in[24];
    float* out = (float*)d_out;

    float *x, *posb, *ob, *tmpb, *boa;
    cudaGetSymbolAddress((void**)&x,    g_x);
    cudaGetSymbolAddress((void**)&posb, g_pos);
    cudaGetSymbolAddress((void**)&ob,   g_off);
    cudaGetSymbolAddress((void**)&tmpb, g_tmp);
    cudaGetSymbolAddress((void**)&boa,  g_boa);

    f16 *vbh, *xh, *qh, *ach, *hh;
    cudaGetSymbolAddress((void**)&vbh, g_valh);
    cudaGetSymbolAddress((void**)&xh,  g_xh);
    cudaGetSymbolAddress((void**)&qh,  g_qh);
    cudaGetSymbolAddress((void**)&ach, g_ach);
    cudaGetSymbolAddress((void**)&hh,  g_hh);

    f16 *wvh, *woah, *wuh, *w1h, *w2h;
    cudaGetSymbolAddress((void**)&wvh,  g_wv_h);
    cudaGetSymbolAddress((void**)&woah, g_woa_h);
    cudaGetSymbolAddress((void**)&wuh,  g_wu_h);
    cudaGetSymbolAddress((void**)&w1h,  g_w1_h);
    cudaGetSymbolAddress((void**)&w2h,  g_w2_h);

    // launch 0: all weight transposes + fp16; launch 1: bias pack
    {
        dim3 blk(32, 32);
        prep_kernel<<<4416, blk>>>(Wv, Wo, Wa, Wout, W1, W2,
                                   wvh, woah, wuh, w1h, w2h);
        bpack_kernel<<<NLAYERS, 384>>>(bo, ba, boa);
    }

    // launch 2: flatten inputs
    {
        dim3 grid(LQ / 32, DMODEL / 32, BATCH);
        dim3 blk(32, 32);
        flatten_kernel<<<grid, blk>>>(src[0], src[1], src[2], src[3],
                                      pos[0], pos[1], pos[2], pos[3],
                                      lenc, x, posb, xh, qh);
    }

    const int sample_blocks = (MROWS * NH * 32) / 256;
    const int ln_blocks = MROWS / 8;

    for (int i = 0; i < NLAYERS; i++) {
        const size_t o64k  = (size_t)i * 256 * 256;
        const size_t o96k  = (size_t)i * 384 * 256;
        const size_t o256k = (size_t)i * 1024 * 256;

        // fused: value(fp16) = x@Wv + bv  ||  offsets+logits = q@[Wo|Wa] + [bo|ba]
        {
            dim3 grid(5, MROWS / 128);
            proj_gemm<<<grid, 256, SMEM_GEMM>>>(
                xh, wvh + o64k, bv + (size_t)i * 256, vbh,
                qh, woah + o96k, boa + (size_t)i * 384, ob);
        }
        // softmax + deformable sampling (fp16 value) -> fp16 acc
        sample_kernel<<<sample_blocks, 256>>>(vbh, ob, ach);
        // output projection
        tcgemm(ach, wuh + o64k, bout + (size_t)i * 256, tmpb, nullptr, 256, 256, 0);
        // x = LN(x + attn); fp16 for W1
        add_ln_kernel<<<ln_blocks, 256>>>(x, tmpb, ln1g + (size_t)i * 256,
                                          ln1b + (size_t)i * 256, x,
                                          xh, nullptr, nullptr, 1);
        // FFN: h = relu(x @ W1 + b1) -> fp16
        tcgemm(xh, w1h + o256k, b1 + (size_t)i * 1024, nullptr, hh, 256, 1024, 1);
        tcgemm(hh, w2h + o256k, b2 + (size_t)i * 256, tmpb, nullptr, 1024, 256, 0);
        // x = LN(x + ffn); fp16 x for next Wv; q = x + pos fp16 for next layer
        const int last = (i == NLAYERS - 1);
        add_ln_kernel<<<ln_blocks, 256>>>(x, tmpb, ln2g + (size_t)i * 256,
                                          ln2b + (size_t)i * 256,
                                          last ? out : x,
                                          xh, posb, qh, last ? 0 : 3);
    }
}

// round 11
// speedup vs baseline: 1.0624x; 1.0624x over previous
#include <cuda_runtime.h>
#include <cuda_fp16.h>
#include <cstdint>

// ---------------- problem constants ----------------
#define BATCH   8
#define DMODEL  256
#define NH      8
#define NLVL    4
#define NPT     4
#define DH      32
#define NLAYERS 6
#define DFF     1024
#define LQ      5440            // 4096 + 1024 + 256 + 64
#define MROWS   (BATCH * LQ)    // 43520

typedef __half f16;

// ---------------- scratch (device globals; no allocation allowed) ----------------
__device__ __align__(16) float g_x   [MROWS * DMODEL];
__device__ __align__(16) float g_pos [MROWS * DMODEL];
__device__ __align__(16) float g_val [MROWS * DMODEL];
__device__ __align__(16) float g_off [MROWS * 384];     // offsets(256)+logits(128)
__device__ __align__(16) float g_tmp [MROWS * DMODEL];

__device__ __align__(16) f16 g_xh [MROWS * DMODEL];
__device__ __align__(16) f16 g_qh [MROWS * DMODEL];
__device__ __align__(16) f16 g_ach[MROWS * DMODEL];
__device__ __align__(16) f16 g_hh [MROWS * DFF];

// fp16 weights, transposed to [N, K] K-major
__device__ __align__(16) f16 g_wv_h [NLAYERS * 256 * 256];
__device__ __align__(16) f16 g_woa_h[NLAYERS * 384 * 256];   // Wo rows 0-255, Wa rows 256-383
__device__ __align__(16) f16 g_wu_h [NLAYERS * 256 * 256];
__device__ __align__(16) f16 g_w1_h [NLAYERS * 1024 * 256];
__device__ __align__(16) f16 g_w2_h [NLAYERS * 256 * 1024];
__device__ __align__(16) float g_boa [NLAYERS * 384];

// ---------------- low-level helpers ----------------
__device__ __forceinline__ uint32_t smem_u32(const void* p) {
    uint32_t a;
    asm("{ .reg .u64 t; cvta.to.shared.u64 t, %1; cvt.u32.u64 %0, t; }"
        : "=r"(a) : "l"(p));
    return a;
}
__device__ __forceinline__ void ldm4(uint32_t* r, uint32_t addr) {
    asm volatile("ldmatrix.sync.aligned.m8n8.x4.shared.b16 {%0,%1,%2,%3}, [%4];"
                 : "=r"(r[0]), "=r"(r[1]), "=r"(r[2]), "=r"(r[3]) : "r"(addr));
}
__device__ __forceinline__ void mma16816(float* c, const uint32_t* a,
                                         const uint32_t* b) {
    asm volatile(
        "mma.sync.aligned.m16n8k16.row.col.f32.f16.f16.f32 "
        "{%0,%1,%2,%3}, {%4,%5,%6,%7}, {%8,%9}, {%0,%1,%2,%3};"
        : "+f"(c[0]), "+f"(c[1]), "+f"(c[2]), "+f"(c[3])
        : "r"(a[0]), "r"(a[1]), "r"(a[2]), "r"(a[3]), "r"(b[0]), "r"(b[1]));
}
__device__ __forceinline__ uint32_t h2u(__half2 v) {
    return *reinterpret_cast<uint32_t*>(&v);
}
#define CP_ASYNC16(d, s) \
    asm volatile("cp.async.cg.shared.global [%0], [%1], 16;" :: "r"(d), "l"(s))
#define CP_COMMIT() asm volatile("cp.async.commit_group;" ::: "memory")
#define CP_WAIT(n)  asm volatile("cp.async.wait_group %0;" :: "n"(n) : "memory")

// ---------------- merged weight prep ----------------
__global__ void prep_kernel(
    const float* __restrict__ Wv, const float* __restrict__ Wo,
    const float* __restrict__ Wa, const float* __restrict__ Wout,
    const float* __restrict__ W1, const float* __restrict__ W2,
    f16* __restrict__ wvh, f16* __restrict__ woah, f16* __restrict__ wuh,
    f16* __restrict__ w1h, f16* __restrict__ w2h)
{
    __shared__ float t[32][33];
    int bid = blockIdx.x;
    const float* W; f16* hi;
    int K, N, Ntot, rowoff, tpl;
    if (bid < 384)       { W = Wv;   hi = wvh;  K = 256;  N = 256;  Ntot = 256;  rowoff = 0;   tpl = 64;  }
    else if (bid < 768)  { bid -= 384;  W = Wo;   hi = woah; K = 256;  N = 256;  Ntot = 384;  rowoff = 0;   tpl = 64;  }
    else if (bid < 960)  { bid -= 768;  W = Wa;   hi = woah; K = 256;  N = 128;  Ntot = 384;  rowoff = 256; tpl = 32;  }
    else if (bid < 1344) { bid -= 960;  W = Wout; hi = wuh;  K = 256;  N = 256;  Ntot = 256;  rowoff = 0;   tpl = 64;  }
    else if (bid < 2880) { bid -= 1344; W = W1;   hi = w1h;  K = 256;  N = 1024; Ntot = 1024; rowoff = 0;   tpl = 256; }
    else                 { bid -= 2880; W = W2;   hi = w2h;  K = 1024; N = 256;  Ntot = 256;  rowoff = 0;   tpl = 256; }
    const int l = bid / tpl, tt = bid % tpl;
    const int nt = N / 32;
    const int n0 = (tt % nt) * 32, k0 = (tt / nt) * 32;

    const float* Wl = W + (size_t)l * K * N;
    t[threadIdx.y][threadIdx.x] = Wl[(size_t)(k0 + threadIdx.y) * N + n0 + threadIdx.x];
    __syncthreads();
    const size_t o = ((size_t)l * Ntot + rowoff + n0 + threadIdx.y) * K + k0 + threadIdx.x;
    hi[o] = __float2half_rn(t[threadIdx.x][threadIdx.y]);
}

__global__ void bpack_kernel(const float* __restrict__ bo, const float* __restrict__ ba,
                             float* __restrict__ boa)
{
    const int l = blockIdx.x, t = threadIdx.x;   // 384 threads
    boa[l * 384 + t] = (t < 256) ? bo[l * 256 + t] : ba[l * 128 + (t - 256)];
}

// ---------------- pipelined fp16 mma.sync GEMM core (single pass) ----------------
// C = A[M,K] @ B[N,K]^T + bias. CTA 128x128, 8 warps 2x4, warp tile 64x32,
// BK=32, cp.async 4-stage pipeline, ONE barrier per chunk.
// mode 0: fp32 out.  mode 1: relu + fp16 out.
#define GPITCH 80
#define TILESZ 10240
#define STGSZ  20480   // A + B
#define NSTG   4

__device__ __forceinline__ void gemm_core(
    const f16* __restrict__ A, const f16* __restrict__ B,
    const float* __restrict__ bias, float* __restrict__ Cf,
    f16* __restrict__ Ch,
    int K, int N, int mode, int m0, int n0, uint8_t* sm)
{
    const uint32_t sb = smem_u32(sm);
    const int tid = threadIdx.x;
    const int wid = tid >> 5, lane = tid & 31;
    const int wm = wid >> 2, wn = wid & 3;
    const int m0w = wm * 64, n0w = wn * 32;
    const int tlq = lane >> 3, rlq = lane & 7;

    const f16* gA = A + (size_t)m0 * K;
    const f16* gB = B + (size_t)n0 * K;

    float acc[4][4][4];
#pragma unroll
    for (int i = 0; i < 4; i++)
#pragma unroll
        for (int j = 0; j < 4; j++)
#pragma unroll
            for (int c = 0; c < 4; c++) acc[i][j][c] = 0.f;

    const int nchunk = K >> 5;

    auto docopy = [&](int ch) {
        const int k0 = ch << 5;
        const uint32_t sbase = sb + (uint32_t)(ch % NSTG) * STGSZ;
#pragma unroll
        for (int j = 0; j < 4; j++) {
            const int buf = j >> 1;                  // 0=A, 1=B
            const int s = tid + ((j & 1) << 8);
            const int row = s >> 2, seg = s & 3;
            const f16* g = (buf ? gB : gA) + (size_t)row * K + k0 + seg * 8;
            const uint32_t d = sbase + buf * TILESZ + row * GPITCH + seg * 16;
            CP_ASYNC16(d, g);
        }
        CP_COMMIT();
    };

    for (int p = 0; p < NSTG - 1 && p < nchunk; p++) docopy(p);
    for (int ch = 0; ch < nchunk; ch++) {
        // wait until chunk ch's group is complete (per-thread), then barrier
        const int rem = nchunk - 1 - ch;   // committed groups beyond ch
        if (rem >= 2)      { CP_WAIT(2); }
        else if (rem == 1) { CP_WAIT(1); }
        else               { CP_WAIT(0); }
        __syncthreads();   // all threads' copies for ch visible; prev compute done
        if (ch + NSTG - 1 < nchunk) docopy(ch + NSTG - 1);  // rewrites stage (ch-1)%4

        const uint32_t soff = sb + (uint32_t)(ch % NSTG) * STGSZ;
#pragma unroll
        for (int ks = 0; ks < 2; ks++) {
            const int kk = ks * 16;
            uint32_t af[16], bfr[8];

#pragma unroll
            for (int mi = 0; mi < 4; mi++) {
                const int r = m0w + mi * 16 + rlq + ((tlq & 1) << 3);
                const int kc = kk + ((tlq >> 1) << 3);
                ldm4(af + mi * 4, soff + r * GPITCH + kc * 2);
            }
#pragma unroll
            for (int nj = 0; nj < 2; nj++) {
                const int r = n0w + nj * 16 + rlq + ((tlq >> 1) << 3);
                const int kc = kk + ((tlq & 1) << 3);
                ldm4(bfr + nj * 4, soff + TILESZ + r * GPITCH + kc * 2);
            }
#pragma unroll
            for (int mi = 0; mi < 4; mi++)
#pragma unroll
                for (int ni = 0; ni < 4; ni++) {
                    uint32_t b2r[2] = {bfr[(ni >> 1) * 4 + (ni & 1) * 2],
                                       bfr[(ni >> 1) * 4 + (ni & 1) * 2 + 1]};
                    mma16816(acc[mi][ni], af + mi * 4, b2r);
                }
        }
    }

    const int g = lane >> 2, tg = lane & 3;
#pragma unroll
    for (int mi = 0; mi < 4; mi++) {
        const int r0 = m0 + m0w + mi * 16 + g;
#pragma unroll
        for (int ni = 0; ni < 4; ni++) {
            const int col = n0 + n0w + ni * 8 + tg * 2;
            const float b0 = bias[col], b1 = bias[col + 1];
            float v00 = acc[mi][ni][0] + b0, v01 = acc[mi][ni][1] + b1;
            float v10 = acc[mi][ni][2] + b0, v11 = acc[mi][ni][3] + b1;
            if (mode == 0) {
                *(float2*)(Cf + (size_t)r0 * N + col)       = make_float2(v00, v01);
                *(float2*)(Cf + (size_t)(r0 + 8) * N + col) = make_float2(v10, v11);
            } else {
                v00 = fmaxf(v00, 0.f); v01 = fmaxf(v01, 0.f);
                v10 = fmaxf(v10, 0.f); v11 = fmaxf(v11, 0.f);
                *(uint32_t*)(Ch + (size_t)r0 * N + col) =
                    h2u(__halves2half2(__float2half_rn(v00), __float2half_rn(v01)));
                *(uint32_t*)(Ch + (size_t)(r0 + 8) * N + col) =
                    h2u(__halves2half2(__float2half_rn(v10), __float2half_rn(v11)));
            }
        }
    }
}

__global__ void __launch_bounds__(256, 2) mma_gemm(
    const f16* __restrict__ A, const f16* __restrict__ B,
    const float* __restrict__ bias, float* __restrict__ Cf,
    f16* __restrict__ Ch, int K, int N, int mode)
{
    extern __shared__ __align__(16) uint8_t sm[];
    gemm_core(A, B, bias, Cf, Ch, K, N, mode,
              blockIdx.y * 128, blockIdx.x * 128, sm);
}

// fused value + offsets/logits projections (independent, share a launch)
// grid.x: 0-1 = value tiles (N=256), 2-4 = proj tiles (N=384)
__global__ void __launch_bounds__(256, 2) proj_gemm(
    const f16* __restrict__ xh, const f16* __restrict__ wvh,
    const float* __restrict__ bv, float* __restrict__ vb,
    const f16* __restrict__ qh, const f16* __restrict__ woah,
    const float* __restrict__ boa, float* __restrict__ ob)
{
    extern __shared__ __align__(16) uint8_t sm[];
    const int m0 = blockIdx.y * 128;
    if (blockIdx.x < 2) {
        gemm_core(xh, wvh, bv, vb, nullptr, 256, 256, 0, m0, blockIdx.x * 128, sm);
    } else {
        gemm_core(qh, woah, boa, ob, nullptr, 256, 384, 0, m0,
                  (blockIdx.x - 2) * 128, sm);
    }
}

// ---------------- non-GEMM kernels ----------------
__device__ __forceinline__ float warp_sum(float v) {
#pragma unroll
    for (int o = 16; o > 0; o >>= 1) v += __shfl_xor_sync(0xffffffffu, v, o);
    return v;
}
__device__ __forceinline__ float half_sum16(float v) {
#pragma unroll
    for (int o = 8; o > 0; o >>= 1) v += __shfl_xor_sync(0xffffffffu, v, o);
    return v;
}
__device__ __forceinline__ float half_max16(float v) {
#pragma unroll
    for (int o = 8; o > 0; o >>= 1) v = fmaxf(v, __shfl_xor_sync(0xffffffffu, v, o));
    return v;
}

// flatten: (B,D,H,W) -> x fp32, pos fp32, x fp16, q=x+pos fp16
__global__ void flatten_kernel(const float* __restrict__ s0, const float* __restrict__ s1,
                               const float* __restrict__ s2, const float* __restrict__ s3,
                               const float* __restrict__ p0, const float* __restrict__ p1,
                               const float* __restrict__ p2, const float* __restrict__ p3,
                               const float* __restrict__ lenc,
                               float* __restrict__ x, float* __restrict__ pos,
                               f16* __restrict__ xh, f16* __restrict__ qh)
{
    __shared__ float ts[32][33];
    __shared__ float tp[32][33];
    const int b  = blockIdx.z;
    const int q0 = blockIdx.x * 32;
    const int d0 = blockIdx.y * 32;

    int l, start, HW;
    const float *src, *pp;
    if (q0 < 4096)      { l = 0; start = 0;    HW = 4096; src = s0; pp = p0; }
    else if (q0 < 5120) { l = 1; start = 4096; HW = 1024; src = s1; pp = p1; }
    else if (q0 < 5376) { l = 2; start = 5120; HW = 256;  src = s2; pp = p2; }
    else                { l = 3; start = 5376; HW = 64;   src = s3; pp = p3; }

    const int pix0 = q0 - start;
    const int tx = threadIdx.x, ty = threadIdx.y;

    long sidx = ((long)b * DMODEL + (d0 + ty)) * HW + pix0 + tx;
    ts[ty][tx] = src[sidx];
    tp[ty][tx] = pp[sidx];
    __syncthreads();

    const int q  = q0 + ty;
    const int dd = d0 + tx;
    const size_t oidx = ((size_t)b * LQ + q) * DMODEL + dd;
    const float xv = ts[tx][ty];
    const float pv = tp[tx][ty] + lenc[l * DMODEL + dd];
    x[oidx]   = xv;
    pos[oidx] = pv;
    xh[oidx] = __float2half_rn(xv);
    qh[oidx] = __float2half_rn(xv + pv);
}

// deformable sampling + fused softmax; one warp per (b,q,h)
// tap-parallel: 4 tap-groups x 8 lanes, each lane holds 4 channels (float4)
__global__ void __launch_bounds__(256) sample_kernel(
    const float* __restrict__ val, const float* __restrict__ proj,
    f16* __restrict__ acch)
{
    const int gwid = (blockIdx.x * blockDim.x + threadIdx.x) >> 5;
    const int lane = threadIdx.x & 31;
    const int h = gwid % NH;
    const int q = (gwid / NH) % LQ;
    const int b = gwid / (NH * LQ);

    const size_t rowq = (size_t)b * LQ + q;
    const float* pr = proj + rowq * 384;

    float lv = pr[256 + h * 16 + (lane & 15)];
    float mx = half_max16(lv);
    float e  = __expf(lv - mx);
    float s  = half_sum16(e);
    const float wgt = e / s;

    int W0, start0;
    if (q < 4096)      { W0 = 64; start0 = 0;    }
    else if (q < 5120) { W0 = 32; start0 = 4096; }
    else if (q < 5376) { W0 = 16; start0 = 5120; }
    else               { W0 = 8;  start0 = 5376; }
    const int pix = q - start0;
    const float refx = ((pix % W0) + 0.5f) / (float)W0;
    const float refy = ((pix / W0) + 0.5f) / (float)W0;

    const float* ob = pr + h * 32;
    const int tap = lane >> 3;
    const int tdx = tap & 1, tdy = tap >> 1;
    const int ch4 = (lane & 7) * 4;

    const int Ls[4] = {64, 32, 16, 8};
    const int Ss[4] = {0, 4096, 5120, 5376};
    float4 a4 = make_float4(0.f, 0.f, 0.f, 0.f);

#pragma unroll
    for (int l = 0; l < NLVL; l++) {
        const int   HH = Ls[l];
        const float fH = (float)HH;
        const float* vb = val + ((size_t)b * LQ + Ss[l]) * (NH * DH) + h * DH + ch4;
#pragma unroll
        for (int p = 0; p < NPT; p++) {
            const int si = l * NPT + p;
            const float ox = ob[si * 2];
            const float oy = ob[si * 2 + 1];
            const float aw = __shfl_sync(0xffffffffu, wgt, si);
            const float xx = refx * fH + ox - 0.5f;
            const float yy = refy * fH + oy - 0.5f;
            const float xf = floorf(xx), yf = floorf(yy);
            const float dx = xx - xf, dy = yy - yf;
            const int xi = (int)xf + tdx;
            const int yi = (int)yf + tdy;
            const float wt = (tdx ? dx : 1.f - dx) * (tdy ? dy : 1.f - dy) * aw;
            if (xi >= 0 && xi < HH && yi >= 0 && yi < HH) {
                const float4 v = *(const float4*)(vb + (size_t)(yi * HH + xi) * (NH * DH));
                a4.x += wt * v.x; a4.y += wt * v.y;
                a4.z += wt * v.z; a4.w += wt * v.w;
            }
        }
    }
#pragma unroll
    for (int o = 8; o <= 16; o <<= 1) {
        a4.x += __shfl_xor_sync(0xffffffffu, a4.x, o);
        a4.y += __shfl_xor_sync(0xffffffffu, a4.y, o);
        a4.z += __shfl_xor_sync(0xffffffffu, a4.z, o);
        a4.w += __shfl_xor_sync(0xffffffffu, a4.w, o);
    }
    if (tap == 0) {
        const size_t oi = (rowq * NH + h) * DH + ch4;
        *(uint2*)(acch + oi) = make_uint2(
            h2u(__halves2half2(__float2half_rn(a4.x), __float2half_rn(a4.y))),
            h2u(__halves2half2(__float2half_rn(a4.z), __float2half_rn(a4.w))));
    }
}

// fused residual-add + LayerNorm (float4-vectorized)
// flags bit0: write oh fp16; bit1: write qh = fp16(out + pos)
__global__ void __launch_bounds__(256) add_ln_kernel(
    const float* __restrict__ x, const float* __restrict__ r,
    const float* __restrict__ g, const float* __restrict__ bta,
    float* __restrict__ out,
    f16* __restrict__ oh,
    const float* __restrict__ pos, f16* __restrict__ qh,
    int flags)
{
    const int row  = blockIdx.x * 8 + (threadIdx.x >> 5);
    const int lane = threadIdx.x & 31;
    const size_t base = (size_t)row * DMODEL;
    const float4* xr = (const float4*)(x + base);
    const float4* rr = (const float4*)(r + base);

    float4 v4[2];
    float sum = 0.f;
#pragma unroll
    for (int k = 0; k < 2; k++) {
        float4 a = xr[lane + 32 * k];
        float4 b = rr[lane + 32 * k];
        a.x += b.x; a.y += b.y; a.z += b.z; a.w += b.w;
        v4[k] = a;
        sum += a.x + a.y + a.z + a.w;
    }
    sum = warp_sum(sum);
    const float mu = sum * (1.f / 256.f);
    float vs = 0.f;
#pragma unroll
    for (int k = 0; k < 2; k++) {
        float dx0 = v4[k].x - mu, dx1 = v4[k].y - mu;
        float dx2 = v4[k].z - mu, dx3 = v4[k].w - mu;
        vs += dx0 * dx0 + dx1 * dx1 + dx2 * dx2 + dx3 * dx3;
    }
    vs = warp_sum(vs) * (1.f / 256.f);
    const float inv = rsqrtf(vs + 1e-5f);

#pragma unroll
    for (int k = 0; k < 2; k++) {
        const int vi = lane + 32 * k;
        const float4 gg = ((const float4*)g)[vi];
        const float4 bb = ((const float4*)bta)[vi];
        float4 o;
        o.x = (v4[k].x - mu) * inv * gg.x + bb.x;
        o.y = (v4[k].y - mu) * inv * gg.y + bb.y;
        o.z = (v4[k].z - mu) * inv * gg.z + bb.z;
        o.w = (v4[k].w - mu) * inv * gg.w + bb.w;
        ((float4*)(out + base))[vi] = o;
        const size_t c = base + (size_t)vi * 4;
        if (flags & 1) {
            *(uint2*)(oh + c) = make_uint2(
                h2u(__halves2half2(__float2half_rn(o.x), __float2half_rn(o.y))),
                h2u(__halves2half2(__float2half_rn(o.z), __float2half_rn(o.w))));
        }
        if (flags & 2) {
            const float4 pv = ((const float4*)(pos + base))[vi];
            *(uint2*)(qh + c) = make_uint2(
                h2u(__halves2half2(__float2half_rn(o.x + pv.x), __float2half_rn(o.y + pv.y))),
                h2u(__halves2half2(__float2half_rn(o.z + pv.z), __float2half_rn(o.w + pv.w))));
        }
    }
}

// ---------------- host orchestration ----------------
#define SMEM_GEMM (NSTG * STGSZ)

static void tcgemm(const f16* A, const f16* B, const float* bias,
                   float* Cf, f16* Ch, int K, int N, int mode)
{
    dim3 grid(N / 128, MROWS / 128);
    mma_gemm<<<grid, 256, SMEM_GEMM>>>(A, B, bias, Cf, Ch, K, N, mode);
}

extern "C" void kernel_launch(void* const* d_in, const int* in_sizes, int n_in,
                              void* d_out, int out_size)
{
    cudaFuncSetAttribute(mma_gemm,  cudaFuncAttributeMaxDynamicSharedMemorySize, SMEM_GEMM);
    cudaFuncSetAttribute(proj_gemm, cudaFuncAttributeMaxDynamicSharedMemorySize, SMEM_GEMM);

    // inputs may arrive interleaved (src0,pos0,src1,pos1,...) per dict order
    const float* src[4];
    const float* pos[4];
    if (in_sizes[1] == in_sizes[0]) {
        for (int i = 0; i < 4; i++) {
            src[i] = (const float*)d_in[2 * i];
            pos[i] = (const float*)d_in[2 * i + 1];
        }
    } else {
        for (int i = 0; i < 4; i++) {
            src[i] = (const float*)d_in[i];
            pos[i] = (const float*)d_in[4 + i];
        }
    }
    const float* lenc  = (const float*)d_in[8];
    const float* Wv    = (const float*)d_in[9];
    const float* bv    = (const float*)d_in[10];
    const float* Wo    = (const float*)d_in[11];
    const float* bo    = (const float*)d_in[12];
    const float* Wa    = (const float*)d_in[13];
    const float* ba    = (const float*)d_in[14];
    const float* Wout  = (const float*)d_in[15];
    const float* bout  = (const float*)d_in[16];
    const float* ln1g  = (const float*)d_in[17];
    const float* ln1b  = (const float*)d_in[18];
    const float* W1    = (const float*)d_in[19];
    const float* b1    = (const float*)d_in[20];
    const float* W2    = (const float*)d_in[21];
    const float* b2    = (const float*)d_in[22];
    const float* ln2g  = (const float*)d_in[23];
    const float* ln2b  = (const float*)d_in[24];
    float* out = (float*)d_out;

    float *x, *posb, *vb, *ob, *tmpb, *boa;
    cudaGetSymbolAddress((void**)&x,    g_x);
    cudaGetSymbolAddress((void**)&posb, g_pos);
    cudaGetSymbolAddress((void**)&vb,   g_val);
    cudaGetSymbolAddress((void**)&ob,   g_off);
    cudaGetSymbolAddress((void**)&tmpb, g_tmp);
    cudaGetSymbolAddress((void**)&boa,  g_boa);

    f16 *xh, *qh, *ach, *hh;
    cudaGetSymbolAddress((void**)&xh,  g_xh);
    cudaGetSymbolAddress((void**)&qh,  g_qh);
    cudaGetSymbolAddress((void**)&ach, g_ach);
    cudaGetSymbolAddress((void**)&hh,  g_hh);

    f16 *wvh, *woah, *wuh, *w1h, *w2h;
    cudaGetSymbolAddress((void**)&wvh,  g_wv_h);
    cudaGetSymbolAddress((void**)&woah, g_woa_h);
    cudaGetSymbolAddress((void**)&wuh,  g_wu_h);
    cudaGetSymbolAddress((void**)&w1h,  g_w1_h);
    cudaGetSymbolAddress((void**)&w2h,  g_w2_h);

    // launch 0: all weight transposes + fp16; launch 1: bias pack
    {
        dim3 blk(32, 32);
        prep_kernel<<<4416, blk>>>(Wv, Wo, Wa, Wout, W1, W2,
                                   wvh, woah, wuh, w1h, w2h);
        bpack_kernel<<<NLAYERS, 384>>>(bo, ba, boa);
    }

    // launch 2: flatten inputs
    {
        dim3 grid(LQ / 32, DMODEL / 32, BATCH);
        dim3 blk(32, 32);
        flatten_kernel<<<grid, blk>>>(src[0], src[1], src[2], src[3],
                                      pos[0], pos[1], pos[2], pos[3],
                                      lenc, x, posb, xh, qh);
    }

    const int sample_blocks = (MROWS * NH * 32) / 256;
    const int ln_blocks = MROWS / 8;

    for (int i = 0; i < NLAYERS; i++) {
        const size_t o64k  = (size_t)i * 256 * 256;
        const size_t o96k  = (size_t)i * 384 * 256;
        const size_t o256k = (size_t)i * 1024 * 256;

        // fused: value = x@Wv + bv  ||  offsets+logits = q@[Wo|Wa] + [bo|ba]
        {
            dim3 grid(5, MROWS / 128);
            proj_gemm<<<grid, 256, SMEM_GEMM>>>(
                xh, wvh + o64k, bv + (size_t)i * 256, vb,
                qh, woah + o96k, boa + (size_t)i * 384, ob);
        }
        // softmax + deformable sampling -> fp16 acc
        sample_kernel<<<sample_blocks, 256>>>(vb, ob, ach);
        // output projection
        tcgemm(ach, wuh + o64k, bout + (size_t)i * 256, tmpb, nullptr, 256, 256, 0);
        // x = LN(x + attn); fp16 for W1
        add_ln_kernel<<<ln_blocks, 256>>>(x, tmpb, ln1g + (size_t)i * 256,
                                          ln1b + (size_t)i * 256, x,
                                          xh, nullptr, nullptr, 1);
        // FFN: h = relu(x @ W1 + b1) -> fp16
        tcgemm(xh, w1h + o256k, b1 + (size_t)i * 1024, nullptr, hh, 256, 1024, 1);
        tcgemm(hh, w2h + o256k, b2 + (size_t)i * 256, tmpb, nullptr, 1024, 256, 0);
        // x = LN(x + ffn); fp16 x for next Wv; q = x + pos fp16 for next layer
        const int last = (i == NLAYERS - 1);
        add_ln_kernel<<<ln_blocks, 256>>>(x, tmpb, ln2g + (size_t)i * 256,
                                          ln2b + (size_t)i * 256,
                                          last ? out : x,
                                          xh, posb, qh, last ? 0 : 3);
    }
}

// round 12
// speedup vs baseline: 1.0698x; 1.0069x over previous
#include <cuda_runtime.h>
#include <cuda_fp16.h>
#include <cstdint>

// ---------------- problem constants ----------------
#define BATCH   8
#define DMODEL  256
#define NH      8
#define NLVL    4
#define NPT     4
#define DH      32
#define NLAYERS 6
#define DFF     1024
#define LQ      5440            // 4096 + 1024 + 256 + 64
#define MROWS   (BATCH * LQ)    // 43520

typedef __half f16;

// ---------------- scratch (device globals; no allocation allowed) ----------------
__device__ __align__(16) float g_x   [MROWS * DMODEL];
__device__ __align__(16) float g_pos [MROWS * DMODEL];
__device__ __align__(16) float g_val [MROWS * DMODEL];
__device__ __align__(16) float g_off [MROWS * 384];     // offsets(256)+logits(128)
__device__ __align__(16) float g_tmp [MROWS * DMODEL];

__device__ __align__(16) f16 g_xh [MROWS * DMODEL];
__device__ __align__(16) f16 g_qh [MROWS * DMODEL];
__device__ __align__(16) f16 g_ach[MROWS * DMODEL];
__device__ __align__(16) f16 g_hh [MROWS * DFF];

// fp16 weights, transposed to [N, K] K-major
__device__ __align__(16) f16 g_wv_h [NLAYERS * 256 * 256];
__device__ __align__(16) f16 g_woa_h[NLAYERS * 384 * 256];   // Wo rows 0-255, Wa rows 256-383
__device__ __align__(16) f16 g_wu_h [NLAYERS * 256 * 256];
__device__ __align__(16) f16 g_w1_h [NLAYERS * 1024 * 256];
__device__ __align__(16) f16 g_w2_h [NLAYERS * 256 * 1024];
__device__ __align__(16) float g_boa [NLAYERS * 384];

// ---------------- low-level helpers ----------------
__device__ __forceinline__ uint32_t smem_u32(const void* p) {
    uint32_t a;
    asm("{ .reg .u64 t; cvta.to.shared.u64 t, %1; cvt.u32.u64 %0, t; }"
        : "=r"(a) : "l"(p));
    return a;
}
__device__ __forceinline__ void ldm4(uint32_t* r, uint32_t addr) {
    asm volatile("ldmatrix.sync.aligned.m8n8.x4.shared.b16 {%0,%1,%2,%3}, [%4];"
                 : "=r"(r[0]), "=r"(r[1]), "=r"(r[2]), "=r"(r[3]) : "r"(addr));
}
__device__ __forceinline__ void mma16816(float* c, const uint32_t* a,
                                         const uint32_t* b) {
    asm volatile(
        "mma.sync.aligned.m16n8k16.row.col.f32.f16.f16.f32 "
        "{%0,%1,%2,%3}, {%4,%5,%6,%7}, {%8,%9}, {%0,%1,%2,%3};"
        : "+f"(c[0]), "+f"(c[1]), "+f"(c[2]), "+f"(c[3])
        : "r"(a[0]), "r"(a[1]), "r"(a[2]), "r"(a[3]), "r"(b[0]), "r"(b[1]));
}
__device__ __forceinline__ uint32_t h2u(__half2 v) {
    return *reinterpret_cast<uint32_t*>(&v);
}
#define CP_ASYNC16(d, s) \
    asm volatile("cp.async.cg.shared.global [%0], [%1], 16;" :: "r"(d), "l"(s))
#define CP_COMMIT() asm volatile("cp.async.commit_group;" ::: "memory")
#define CP_WAIT(n)  asm volatile("cp.async.wait_group %0;" :: "n"(n) : "memory")

// ---------------- merged weight prep ----------------
__global__ void prep_kernel(
    const float* __restrict__ Wv, const float* __restrict__ Wo,
    const float* __restrict__ Wa, const float* __restrict__ Wout,
    const float* __restrict__ W1, const float* __restrict__ W2,
    f16* __restrict__ wvh, f16* __restrict__ woah, f16* __restrict__ wuh,
    f16* __restrict__ w1h, f16* __restrict__ w2h)
{
    __shared__ float t[32][33];
    int bid = blockIdx.x;
    const float* W; f16* hi;
    int K, N, Ntot, rowoff, tpl;
    if (bid < 384)       { W = Wv;   hi = wvh;  K = 256;  N = 256;  Ntot = 256;  rowoff = 0;   tpl = 64;  }
    else if (bid < 768)  { bid -= 384;  W = Wo;   hi = woah; K = 256;  N = 256;  Ntot = 384;  rowoff = 0;   tpl = 64;  }
    else if (bid < 960)  { bid -= 768;  W = Wa;   hi = woah; K = 256;  N = 128;  Ntot = 384;  rowoff = 256; tpl = 32;  }
    else if (bid < 1344) { bid -= 960;  W = Wout; hi = wuh;  K = 256;  N = 256;  Ntot = 256;  rowoff = 0;   tpl = 64;  }
    else if (bid < 2880) { bid -= 1344; W = W1;   hi = w1h;  K = 256;  N = 1024; Ntot = 1024; rowoff = 0;   tpl = 256; }
    else                 { bid -= 2880; W = W2;   hi = w2h;  K = 1024; N = 256;  Ntot = 256;  rowoff = 0;   tpl = 256; }
    const int l = bid / tpl, tt = bid % tpl;
    const int nt = N / 32;
    const int n0 = (tt % nt) * 32, k0 = (tt / nt) * 32;

    const float* Wl = W + (size_t)l * K * N;
    t[threadIdx.y][threadIdx.x] = Wl[(size_t)(k0 + threadIdx.y) * N + n0 + threadIdx.x];
    __syncthreads();
    const size_t o = ((size_t)l * Ntot + rowoff + n0 + threadIdx.y) * K + k0 + threadIdx.x;
    hi[o] = __float2half_rn(t[threadIdx.x][threadIdx.y]);
}

__global__ void bpack_kernel(const float* __restrict__ bo, const float* __restrict__ ba,
                             float* __restrict__ boa)
{
    const int l = blockIdx.x, t = threadIdx.x;   // 384 threads
    boa[l * 384 + t] = (t < 256) ? bo[l * 256 + t] : ba[l * 128 + (t - 256)];
}

// ---------------- pipelined fp16 mma.sync GEMM core ----------------
// C = A[M,K] @ B[N,K]^T + bias. CTA 128x128, 8 warps 2x4, warp tile 64x32.
// BK=64 chunks (two 32-K subtiles), 2-stage ping-pong, ONE barrier per chunk.
// K is compile-time. mode 0: fp32 out.  mode 1: relu + fp16 out.
#define GPITCH 80
#define TILESZ 10240          // one 128x32 (or N-rows x 32) f16 subtile
#define STGSZ  40960          // A0 A1 B0 B1
#define SMEM_GEMM (2 * STGSZ) // 81920

template<int KC>
__device__ __forceinline__ void gemm_core(
    const f16* __restrict__ A, const f16* __restrict__ B,
    const float* __restrict__ bias, float* __restrict__ Cf,
    f16* __restrict__ Ch,
    int N, int mode, int m0, int n0, uint8_t* sm)
{
    const uint32_t sb = smem_u32(sm);
    const int tid = threadIdx.x;
    const int wid = tid >> 5, lane = tid & 31;
    const int wm = wid >> 2, wn = wid & 3;
    const int m0w = wm * 64, n0w = wn * 32;
    const int tlq = lane >> 3, rlq = lane & 7;

    const f16* gA = A + (size_t)m0 * KC;
    const f16* gB = B + (size_t)n0 * KC;

    float acc[4][4][4];
#pragma unroll
    for (int i = 0; i < 4; i++)
#pragma unroll
        for (int j = 0; j < 4; j++)
#pragma unroll
            for (int c = 0; c < 4; c++) acc[i][j][c] = 0.f;

    constexpr int NCHUNK = KC >> 6;

    auto docopy = [&](int ch) {
        const int k0 = ch << 6;
        const uint32_t sbase = sb + (uint32_t)(ch & 1) * STGSZ;
#pragma unroll
        for (int j = 0; j < 8; j++) {
            const int t = j >> 1;              // 0,1 = A sub0/1; 2,3 = B sub0/1
            const int s = tid + ((j & 1) << 8);
            const int row = s >> 2, seg = s & 3;
            const f16* g = (t < 2 ? gA : gB)
                           + (size_t)row * KC + k0 + ((t & 1) << 5) + seg * 8;
            const uint32_t d = sbase + t * TILESZ + row * GPITCH + seg * 16;
            CP_ASYNC16(d, g);
        }
        CP_COMMIT();
    };

    docopy(0);
#pragma unroll 1
    for (int ch = 0; ch < NCHUNK; ch++) {
        CP_WAIT(0);
        __syncthreads();                 // all copies for ch visible; prev compute done
        if (ch + 1 < NCHUNK) docopy(ch + 1);   // fills other stage, overlaps compute

        const uint32_t soff = sb + (uint32_t)(ch & 1) * STGSZ;
#pragma unroll
        for (int ks = 0; ks < 4; ks++) {
            const uint32_t abase = soff + (uint32_t)(ks >> 1) * TILESZ;
            const uint32_t bbase = soff + (uint32_t)(2 + (ks >> 1)) * TILESZ;
            const int kk = (ks & 1) * 16;
            uint32_t af[16], bfr[8];

#pragma unroll
            for (int mi = 0; mi < 4; mi++) {
                const int r = m0w + mi * 16 + rlq + ((tlq & 1) << 3);
                const int kc = kk + ((tlq >> 1) << 3);
                ldm4(af + mi * 4, abase + r * GPITCH + kc * 2);
            }
#pragma unroll
            for (int nj = 0; nj < 2; nj++) {
                const int r = n0w + nj * 16 + rlq + ((tlq >> 1) << 3);
                const int kc = kk + ((tlq & 1) << 3);
                ldm4(bfr + nj * 4, bbase + r * GPITCH + kc * 2);
            }
#pragma unroll
            for (int mi = 0; mi < 4; mi++)
#pragma unroll
                for (int ni = 0; ni < 4; ni++) {
                    uint32_t b2r[2] = {bfr[(ni >> 1) * 4 + (ni & 1) * 2],
                                       bfr[(ni >> 1) * 4 + (ni & 1) * 2 + 1]};
                    mma16816(acc[mi][ni], af + mi * 4, b2r);
                }
        }
    }

    const int g = lane >> 2, tg = lane & 3;
#pragma unroll
    for (int mi = 0; mi < 4; mi++) {
        const int r0 = m0 + m0w + mi * 16 + g;
#pragma unroll
        for (int ni = 0; ni < 4; ni++) {
            const int col = n0 + n0w + ni * 8 + tg * 2;
            const float b0 = bias[col], b1 = bias[col + 1];
            float v00 = acc[mi][ni][0] + b0, v01 = acc[mi][ni][1] + b1;
            float v10 = acc[mi][ni][2] + b0, v11 = acc[mi][ni][3] + b1;
            if (mode == 0) {
                *(float2*)(Cf + (size_t)r0 * N + col)       = make_float2(v00, v01);
                *(float2*)(Cf + (size_t)(r0 + 8) * N + col) = make_float2(v10, v11);
            } else {
                v00 = fmaxf(v00, 0.f); v01 = fmaxf(v01, 0.f);
                v10 = fmaxf(v10, 0.f); v11 = fmaxf(v11, 0.f);
                *(uint32_t*)(Ch + (size_t)r0 * N + col) =
                    h2u(__halves2half2(__float2half_rn(v00), __float2half_rn(v01)));
                *(uint32_t*)(Ch + (size_t)(r0 + 8) * N + col) =
                    h2u(__halves2half2(__float2half_rn(v10), __float2half_rn(v11)));
            }
        }
    }
}

template<int KC>
__global__ void __launch_bounds__(256, 2) mma_gemm(
    const f16* __restrict__ A, const f16* __restrict__ B,
    const float* __restrict__ bias, float* __restrict__ Cf,
    f16* __restrict__ Ch, int N, int mode)
{
    extern __shared__ __align__(16) uint8_t sm[];
    gemm_core<KC>(A, B, bias, Cf, Ch, N, mode,
                  blockIdx.y * 128, blockIdx.x * 128, sm);
}

// fused value + offsets/logits projections (independent, share a launch)
// grid.x: 0-1 = value tiles (N=256), 2-4 = proj tiles (N=384)
__global__ void __launch_bounds__(256, 2) proj_gemm(
    const f16* __restrict__ xh, const f16* __restrict__ wvh,
    const float* __restrict__ bv, float* __restrict__ vb,
    const f16* __restrict__ qh, const f16* __restrict__ woah,
    const float* __restrict__ boa, float* __restrict__ ob)
{
    extern __shared__ __align__(16) uint8_t sm[];
    const int m0 = blockIdx.y * 128;
    if (blockIdx.x < 2) {
        gemm_core<256>(xh, wvh, bv, vb, nullptr, 256, 0, m0, blockIdx.x * 128, sm);
    } else {
        gemm_core<256>(qh, woah, boa, ob, nullptr, 384, 0, m0,
                       (blockIdx.x - 2) * 128, sm);
    }
}

// ---------------- non-GEMM kernels ----------------
__device__ __forceinline__ float warp_sum(float v) {
#pragma unroll
    for (int o = 16; o > 0; o >>= 1) v += __shfl_xor_sync(0xffffffffu, v, o);
    return v;
}
__device__ __forceinline__ float half_sum16(float v) {
#pragma unroll
    for (int o = 8; o > 0; o >>= 1) v += __shfl_xor_sync(0xffffffffu, v, o);
    return v;
}
__device__ __forceinline__ float half_max16(float v) {
#pragma unroll
    for (int o = 8; o > 0; o >>= 1) v = fmaxf(v, __shfl_xor_sync(0xffffffffu, v, o));
    return v;
}

// flatten: (B,D,H,W) -> x fp32, pos fp32, x fp16, q=x+pos fp16
__global__ void flatten_kernel(const float* __restrict__ s0, const float* __restrict__ s1,
                               const float* __restrict__ s2, const float* __restrict__ s3,
                               const float* __restrict__ p0, const float* __restrict__ p1,
                               const float* __restrict__ p2, const float* __restrict__ p3,
                               const float* __restrict__ lenc,
                               float* __restrict__ x, float* __restrict__ pos,
                               f16* __restrict__ xh, f16* __restrict__ qh)
{
    __shared__ float ts[32][33];
    __shared__ float tp[32][33];
    const int b  = blockIdx.z;
    const int q0 = blockIdx.x * 32;
    const int d0 = blockIdx.y * 32;

    int l, start, HW;
    const float *src, *pp;
    if (q0 < 4096)      { l = 0; start = 0;    HW = 4096; src = s0; pp = p0; }
    else if (q0 < 5120) { l = 1; start = 4096; HW = 1024; src = s1; pp = p1; }
    else if (q0 < 5376) { l = 2; start = 5120; HW = 256;  src = s2; pp = p2; }
    else                { l = 3; start = 5376; HW = 64;   src = s3; pp = p3; }

    const int pix0 = q0 - start;
    const int tx = threadIdx.x, ty = threadIdx.y;

    long sidx = ((long)b * DMODEL + (d0 + ty)) * HW + pix0 + tx;
    ts[ty][tx] = src[sidx];
    tp[ty][tx] = pp[sidx];
    __syncthreads();

    const int q  = q0 + ty;
    const int dd = d0 + tx;
    const size_t oidx = ((size_t)b * LQ + q) * DMODEL + dd;
    const float xv = ts[tx][ty];
    const float pv = tp[tx][ty] + lenc[l * DMODEL + dd];
    x[oidx]   = xv;
    pos[oidx] = pv;
    xh[oidx] = __float2half_rn(xv);
    qh[oidx] = __float2half_rn(xv + pv);
}

// deformable sampling + fused softmax; one warp per (b,q,h)
// tap-parallel: 4 tap-groups x 8 lanes, each lane holds 4 channels (float4)
__global__ void __launch_bounds__(256) sample_kernel(
    const float* __restrict__ val, const float* __restrict__ proj,
    f16* __restrict__ acch)
{
    const int gwid = (blockIdx.x * blockDim.x + threadIdx.x) >> 5;
    const int lane = threadIdx.x & 31;
    const int h = gwid % NH;
    const int q = (gwid / NH) % LQ;
    const int b = gwid / (NH * LQ);

    const size_t rowq = (size_t)b * LQ + q;
    const float* pr = proj + rowq * 384;

    float lv = pr[256 + h * 16 + (lane & 15)];
    float mx = half_max16(lv);
    float e  = __expf(lv - mx);
    float s  = half_sum16(e);
    const float wgt = e / s;

    int W0, start0;
    if (q < 4096)      { W0 = 64; start0 = 0;    }
    else if (q < 5120) { W0 = 32; start0 = 4096; }
    else if (q < 5376) { W0 = 16; start0 = 5120; }
    else               { W0 = 8;  start0 = 5376; }
    const int pix = q - start0;
    const float refx = ((pix % W0) + 0.5f) / (float)W0;
    const float refy = ((pix / W0) + 0.5f) / (float)W0;

    const float* ob = pr + h * 32;
    const int tap = lane >> 3;
    const int tdx = tap & 1, tdy = tap >> 1;
    const int ch4 = (lane & 7) * 4;

    const int Ls[4] = {64, 32, 16, 8};
    const int Ss[4] = {0, 4096, 5120, 5376};
    float4 a4 = make_float4(0.f, 0.f, 0.f, 0.f);

#pragma unroll
    for (int l = 0; l < NLVL; l++) {
        const int   HH = Ls[l];
        const float fH = (float)HH;
        const float* vb = val + ((size_t)b * LQ + Ss[l]) * (NH * DH) + h * DH + ch4;
#pragma unroll
        for (int p = 0; p < NPT; p++) {
            const int si = l * NPT + p;
            const float2 o2 = *(const float2*)(ob + si * 2);   // one LDG.64 (broadcast)
            const float aw = __shfl_sync(0xffffffffu, wgt, si);
            const float xx = fmaf(refx, fH, o2.x - 0.5f);
            const float yy = fmaf(refy, fH, o2.y - 0.5f);
            const int x0i = __float2int_rd(xx);
            const int y0i = __float2int_rd(yy);
            const float dx = xx - (float)x0i;
            const float dy = yy - (float)y0i;
            const int xi = x0i + tdx;
            const int yi = y0i + tdy;
            const float wt = (tdx ? dx : 1.f - dx) * (tdy ? dy : 1.f - dy) * aw;
            if ((unsigned)xi < (unsigned)HH && (unsigned)yi < (unsigned)HH) {
                const float4 v = *(const float4*)(vb + (size_t)(yi * HH + xi) * (NH * DH));
                a4.x += wt * v.x; a4.y += wt * v.y;
                a4.z += wt * v.z; a4.w += wt * v.w;
            }
        }
    }
#pragma unroll
    for (int o = 8; o <= 16; o <<= 1) {
        a4.x += __shfl_xor_sync(0xffffffffu, a4.x, o);
        a4.y += __shfl_xor_sync(0xffffffffu, a4.y, o);
        a4.z += __shfl_xor_sync(0xffffffffu, a4.z, o);
        a4.w += __shfl_xor_sync(0xffffffffu, a4.w, o);
    }
    if (tap == 0) {
        const size_t oi = (rowq * NH + h) * DH + ch4;
        *(uint2*)(acch + oi) = make_uint2(
            h2u(__halves2half2(__float2half_rn(a4.x), __float2half_rn(a4.y))),
            h2u(__halves2half2(__float2half_rn(a4.z), __float2half_rn(a4.w))));
    }
}

// fused residual-add + LayerNorm (float4-vectorized)
// flags bit0: write oh fp16; bit1: write qh = fp16(out + pos)
__global__ void __launch_bounds__(256) add_ln_kernel(
    const float* __restrict__ x, const float* __restrict__ r,
    const float* __restrict__ g, const float* __restrict__ bta,
    float* __restrict__ out,
    f16* __restrict__ oh,
    const float* __restrict__ pos, f16* __restrict__ qh,
    int flags)
{
    const int row  = blockIdx.x * 8 + (threadIdx.x >> 5);
    const int lane = threadIdx.x & 31;
    const size_t base = (size_t)row * DMODEL;
    const float4* xr = (const float4*)(x + base);
    const float4* rr = (const float4*)(r + base);

    float4 v4[2];
    float sum = 0.f;
#pragma unroll
    for (int k = 0; k < 2; k++) {
        float4 a = xr[lane + 32 * k];
        float4 b = rr[lane + 32 * k];
        a.x += b.x; a.y += b.y; a.z += b.z; a.w += b.w;
        v4[k] = a;
        sum += a.x + a.y + a.z + a.w;
    }
    sum = warp_sum(sum);
    const float mu = sum * (1.f / 256.f);
    float vs = 0.f;
#pragma unroll
    for (int k = 0; k < 2; k++) {
        float dx0 = v4[k].x - mu, dx1 = v4[k].y - mu;
        float dx2 = v4[k].z - mu, dx3 = v4[k].w - mu;
        vs += dx0 * dx0 + dx1 * dx1 + dx2 * dx2 + dx3 * dx3;
    }
    vs = warp_sum(vs) * (1.f / 256.f);
    const float inv = rsqrtf(vs + 1e-5f);

#pragma unroll
    for (int k = 0; k < 2; k++) {
        const int vi = lane + 32 * k;
        const float4 gg = ((const float4*)g)[vi];
        const float4 bb = ((const float4*)bta)[vi];
        float4 o;
        o.x = (v4[k].x - mu) * inv * gg.x + bb.x;
        o.y = (v4[k].y - mu) * inv * gg.y + bb.y;
        o.z = (v4[k].z - mu) * inv * gg.z + bb.z;
        o.w = (v4[k].w - mu) * inv * gg.w + bb.w;
        ((float4*)(out + base))[vi] = o;
        const size_t c = base + (size_t)vi * 4;
        if (flags & 1) {
            *(uint2*)(oh + c) = make_uint2(
                h2u(__halves2half2(__float2half_rn(o.x), __float2half_rn(o.y))),
                h2u(__halves2half2(__float2half_rn(o.z), __float2half_rn(o.w))));
        }
        if (flags & 2) {
            const float4 pv = ((const float4*)(pos + base))[vi];
            *(uint2*)(qh + c) = make_uint2(
                h2u(__halves2half2(__float2half_rn(o.x + pv.x), __float2half_rn(o.y + pv.y))),
                h2u(__halves2half2(__float2half_rn(o.z + pv.z), __float2half_rn(o.w + pv.w))));
        }
    }
}

// ---------------- host orchestration ----------------
static void tcgemm(const f16* A, const f16* B, const float* bias,
                   float* Cf, f16* Ch, int K, int N, int mode)
{
    dim3 grid(N / 128, MROWS / 128);
    if (K == 256)
        mma_gemm<256><<<grid, 256, SMEM_GEMM>>>(A, B, bias, Cf, Ch, N, mode);
    else
        mma_gemm<1024><<<grid, 256, SMEM_GEMM>>>(A, B, bias, Cf, Ch, N, mode);
}

extern "C" void kernel_launch(void* const* d_in, const int* in_sizes, int n_in,
                              void* d_out, int out_size)
{
    cudaFuncSetAttribute(mma_gemm<256>,  cudaFuncAttributeMaxDynamicSharedMemorySize, SMEM_GEMM);
    cudaFuncSetAttribute(mma_gemm<1024>, cudaFuncAttributeMaxDynamicSharedMemorySize, SMEM_GEMM);
    cudaFuncSetAttribute(proj_gemm,      cudaFuncAttributeMaxDynamicSharedMemorySize, SMEM_GEMM);

    // inputs may arrive interleaved (src0,pos0,src1,pos1,...) per dict order
    const float* src[4];
    const float* pos[4];
    if (in_sizes[1] == in_sizes[0]) {
        for (int i = 0; i < 4; i++) {
            src[i] = (const float*)d_in[2 * i];
            pos[i] = (const float*)d_in[2 * i + 1];
        }
    } else {
        for (int i = 0; i < 4; i++) {
            src[i] = (const float*)d_in[i];
            pos[i] = (const float*)d_in[4 + i];
        }
    }
    const float* lenc  = (const float*)d_in[8];
    const float* Wv    = (const float*)d_in[9];
    const float* bv    = (const float*)d_in[10];
    const float* Wo    = (const float*)d_in[11];
    const float* bo    = (const float*)d_in[12];
    const float* Wa    = (const float*)d_in[13];
    const float* ba    = (const float*)d_in[14];
    const float* Wout  = (const float*)d_in[15];
    const float* bout  = (const float*)d_in[16];
    const float* ln1g  = (const float*)d_in[17];
    const float* ln1b  = (const float*)d_in[18];
    const float* W1    = (const float*)d_in[19];
    const float* b1    = (const float*)d_in[20];
    const float* W2    = (const float*)d_in[21];
    const float* b2    = (const float*)d_in[22];
    const float* ln2g  = (const float*)d_in[23];
    const float* ln2b  = (const float*)d_in[24];
    float* out = (float*)d_out;

    float *x, *posb, *vb, *ob, *tmpb, *boa;
    cudaGetSymbolAddress((void**)&x,    g_x);
    cudaGetSymbolAddress((void**)&posb, g_pos);
    cudaGetSymbolAddress((void**)&vb,   g_val);
    cudaGetSymbolAddress((void**)&ob,   g_off);
    cudaGetSymbolAddress((void**)&tmpb, g_tmp);
    cudaGetSymbolAddress((void**)&boa,  g_boa);

    f16 *xh, *qh, *ach, *hh;
    cudaGetSymbolAddress((void**)&xh,  g_xh);
    cudaGetSymbolAddress((void**)&qh,  g_qh);
    cudaGetSymbolAddress((void**)&ach, g_ach);
    cudaGetSymbolAddress((void**)&hh,  g_hh);

    f16 *wvh, *woah, *wuh, *w1h, *w2h;
    cudaGetSymbolAddress((void**)&wvh,  g_wv_h);
    cudaGetSymbolAddress((void**)&woah, g_woa_h);
    cudaGetSymbolAddress((void**)&wuh,  g_wu_h);
    cudaGetSymbolAddress((void**)&w1h,  g_w1_h);
    cudaGetSymbolAddress((void**)&w2h,  g_w2_h);

    // launch 0: all weight transposes + fp16; launch 1: bias pack
    {
        dim3 blk(32, 32);
        prep_kernel<<<4416, blk>>>(Wv, Wo, Wa, Wout, W1, W2,
                                   wvh, woah, wuh, w1h, w2h);
        bpack_kernel<<<NLAYERS, 384>>>(bo, ba, boa);
    }

    // launch 2: flatten inputs
    {
        dim3 grid(LQ / 32, DMODEL / 32, BATCH);
        dim3 blk(32, 32);
        flatten_kernel<<<grid, blk>>>(src[0], src[1], src[2], src[3],
                                      pos[0], pos[1], pos[2], pos[3],
                                      lenc, x, posb, xh, qh);
    }

    const int sample_blocks = (MROWS * NH * 32) / 256;
    const int ln_blocks = MROWS / 8;

    for (int i = 0; i < NLAYERS; i++) {
        const size_t o64k  = (size_t)i * 256 * 256;
        const size_t o96k  = (size_t)i * 384 * 256;
        const size_t o256k = (size_t)i * 1024 * 256;

        // fused: value = x@Wv + bv  ||  offsets+logits = q@[Wo|Wa] + [bo|ba]
        {
            dim3 grid(5, MROWS / 128);
            proj_gemm<<<grid, 256, SMEM_GEMM>>>(
                xh, wvh + o64k, bv + (size_t)i * 256, vb,
                qh, woah + o96k, boa + (size_t)i * 384, ob);
        }
        // softmax + deformable sampling -> fp16 acc
        sample_kernel<<<sample_blocks, 256>>>(vb, ob, ach);
        // output projection
        tcgemm(ach, wuh + o64k, bout + (size_t)i * 256, tmpb, nullptr, 256, 256, 0);
        // x = LN(x + attn); fp16 for W1
        add_ln_kernel<<<ln_blocks, 256>>>(x, tmpb, ln1g + (size_t)i * 256,
                                          ln1b + (size_t)i * 256, x,
                                          xh, nullptr, nullptr, 1);
        // FFN: h = relu(x @ W1 + b1) -> fp16
        tcgemm(xh, w1h + o256k, b1 + (size_t)i * 1024, nullptr, hh, 256, 1024, 1);
        tcgemm(hh, w2h + o256k, b2 + (size_t)i * 256, tmpb, nullptr, 1024, 256, 0);
        // x = LN(x + ffn); fp16 x for next Wv; q = x + pos fp16 for next layer
        const int last = (i == NLAYERS - 1);
        add_ln_kernel<<<ln_blocks, 256>>>(x, tmpb, ln2g + (size_t)i * 256,
                                          ln2b + (size_t)i * 256,
                                          last ? out : x,
                                          xh, posb, qh, last ? 0 : 3);
    }
}